// round 1
// baseline (speedup 1.0000x reference)
#include <cuda_runtime.h>
#include <cuda_bf16.h>
#include <cstdint>

#define NN 50000
#define EE 800000
#define INF 16
#define HH 64

// ---------------- scratch (static device globals; no allocs) ----------------
__device__ float g_h[NN * HH];
__device__ float g_hnew[NN * HH];
__device__ float g_a1[NN];
__device__ float g_a2[NN];
__device__ int   g_cnt[NN];
__device__ int   g_off[NN + 1];
__device__ int   g_cur[NN];
__device__ int   g_csr_src[EE];

typedef unsigned long long ull;

__device__ __forceinline__ ull pk2(float a, float b) {
    ull r;
    asm("mov.b64 %0, {%1, %2};" : "=l"(r) : "f"(a), "f"(b));
    return r;
}
__device__ __forceinline__ void fma2(ull &d, ull a, ull b) {
    asm("fma.rn.f32x2 %0, %1, %2, %0;" : "+l"(d) : "l"(a), "l"(b));
}
__device__ __forceinline__ float2 un2(ull v) {
    float2 f;
    asm("mov.b64 {%0, %1}, %2;" : "=f"(f.x), "=f"(f.y) : "l"(v));
    return f;
}
__device__ __forceinline__ float sigm(float x) {
    return 1.0f / (1.0f + __expf(-x));
}
__device__ __forceinline__ float tanh_fast(float x) {
    return 2.0f / (1.0f + __expf(-2.0f * x)) - 1.0f;
}

// ---------------- CSR build ----------------
__global__ void k_zero(int n) {
    int i = blockIdx.x * blockDim.x + threadIdx.x;
    if (i < n) g_cnt[i] = 0;
}

__global__ void k_count(const int* __restrict__ dst, int e) {
    int i = blockIdx.x * blockDim.x + threadIdx.x;
    if (i < e) atomicAdd(&g_cnt[dst[i]], 1);
}

// single-block exclusive scan of g_cnt[0..n) -> g_off, g_cur ; g_off[n] = total
__global__ void k_scan(int n) {
    __shared__ int sh_carry;
    __shared__ int wsum[32];
    int tid = threadIdx.x;
    if (tid == 0) sh_carry = 0;
    __syncthreads();
    for (int base = 0; base < n; base += 1024) {
        int i = base + tid;
        int v = (i < n) ? g_cnt[i] : 0;
        int x = v;
        #pragma unroll
        for (int d = 1; d < 32; d <<= 1) {
            int y = __shfl_up_sync(0xffffffffu, x, d);
            if ((tid & 31) >= d) x += y;
        }
        if ((tid & 31) == 31) wsum[tid >> 5] = x;
        __syncthreads();
        if (tid < 32) {
            int y = wsum[tid];
            #pragma unroll
            for (int d = 1; d < 32; d <<= 1) {
                int z = __shfl_up_sync(0xffffffffu, y, d);
                if (tid >= d) y += z;
            }
            wsum[tid] = y;
        }
        __syncthreads();
        int excl = ((tid >> 5) ? wsum[(tid >> 5) - 1] : 0) + (x - v);
        int carry = sh_carry;
        if (i < n) { g_off[i] = carry + excl; g_cur[i] = carry + excl; }
        __syncthreads();
        if (tid == 1023) sh_carry = carry + excl + v;
        __syncthreads();
    }
    if (tid == 0) g_off[n] = sh_carry;
}

__global__ void k_fill(const int* __restrict__ src, const int* __restrict__ dst, int e) {
    int i = blockIdx.x * blockDim.x + threadIdx.x;
    if (i < e) {
        int d = dst[i];
        int p = atomicAdd(&g_cur[d], 1);
        g_csr_src[p] = src[i];
    }
}

// ---------------- input linear: h = feat @ W_in + b_in ----------------
__global__ void k_input(const float* __restrict__ feat, const float* __restrict__ Win,
                        const float* __restrict__ bin, int n) {
    __shared__ float sw[INF * HH];
    __shared__ float sb[HH];
    int tid = threadIdx.x;
    for (int i = tid; i < INF * HH; i += 256) sw[i] = Win[i];
    if (tid < HH) sb[tid] = bin[tid];
    __syncthreads();
    int idx = blockIdx.x * 256 + tid;
    if (idx < n * HH) {
        int node = idx >> 6, f = idx & 63;
        float acc = sb[f];
        const float* fr = feat + node * INF;
        #pragma unroll
        for (int i = 0; i < INF; i++) acc = fmaf(fr[i], sw[i * HH + f], acc);
        g_h[idx] = acc;
    }
}

// ---------------- per-node dots: a1 = h . W[0:64], a2 = h . W[64:128] ----------------
// mode 0 -> g_a1/g_a2 ; mode 1 -> reuse g_a1/g_a2 for predictor
__global__ void k_dots(const float* __restrict__ W, int n) {
    __shared__ float sw[128];
    int tid = threadIdx.x;
    if (tid < 128) sw[tid] = W[tid];
    __syncthreads();
    int v = blockIdx.x * 8 + (tid >> 5);
    int lane = tid & 31;
    if (v >= n) return;
    float h0 = g_h[v * HH + lane];
    float h1 = g_h[v * HH + 32 + lane];
    float s1 = h0 * sw[lane] + h1 * sw[32 + lane];
    float s2 = h0 * sw[64 + lane] + h1 * sw[96 + lane];
    #pragma unroll
    for (int d = 16; d; d >>= 1) {
        s1 += __shfl_xor_sync(0xffffffffu, s1, d);
        s2 += __shfl_xor_sync(0xffffffffu, s2, d);
    }
    if (lane == 0) { g_a1[v] = s1; g_a2[v] = s2; }
}

// ---------------- aggregation: hnew[v] = sum_{e: dst=v} sigm(a1[src]+a2[v]+b)*h[src] ----------------
__global__ void k_agg(const float* __restrict__ bedge, int n) {
    int v = blockIdx.x * 8 + (threadIdx.x >> 5);
    int lane = threadIdx.x & 31;
    if (v >= n) return;
    float a2v = g_a2[v] + bedge[0];
    int j0 = g_off[v], j1 = g_off[v + 1];
    float2 acc = make_float2(0.f, 0.f);
    for (int j = j0; j < j1; j++) {
        int s = __ldg(&g_csr_src[j]);
        float w = sigm(g_a1[s] + a2v);
        float2 hv = *(const float2*)&g_h[s * HH + 2 * lane];
        acc.x = fmaf(w, hv.x, acc.x);
        acc.y = fmaf(w, hv.y, acc.y);
    }
    *(float2*)&g_hnew[v * HH + 2 * lane] = acc;
}

// ---------------- fused GRU: G = [hnew@Wih^T | h@Whh^T], then gates ----------------
#define MTILE 32
#define WS 388   // smem stride for 384 outputs (16B aligned, bank-spread)
#define SAS 36   // smem stride for 32 nodes

__global__ void __launch_bounds__(256, 1)
k_gru(const float* __restrict__ Wih, const float* __restrict__ Whh,
      const float* __restrict__ bih, const float* __restrict__ bhh, int n) {
    extern __shared__ float sm[];
    float* sW = sm;                      // [64][WS]  : col o<192 = Wih[o][k], o>=192 = Whh[o-192][k]
    float* sA = sm + 64 * WS;            // [2][64][SAS] k-major A tiles (hnew, h)
    float* sG = sA + 2 * 64 * SAS;       // [32][384]

    int tid = threadIdx.x;

    for (int idx = tid; idx < 192 * 64; idx += 256) {
        int o = idx >> 6, k = idx & 63;
        sW[k * WS + o]       = Wih[idx];
        sW[k * WS + 192 + o] = Whh[idx];
    }
    __syncthreads();

    int og = tid >> 3;            // 0..31 -> 12 outputs each
    int ng = tid & 7;             // 0..7  -> 4 nodes each
    int obase = og * 12;
    const float* sAh = sA + ((og >= 16) ? 64 * SAS : 0);  // gi half uses hnew, gh half uses h

    int ntiles = (n + MTILE - 1) / MTILE;
    for (int tile = blockIdx.x; tile < ntiles; tile += gridDim.x) {
        int n0 = tile * MTILE;

        for (int idx = tid; idx < MTILE * 64; idx += 256) {
            int node = idx >> 6, k = idx & 63;
            int gn = n0 + node;
            float v0 = 0.f, v1 = 0.f;
            if (gn < n) { v0 = g_hnew[gn * HH + k]; v1 = g_h[gn * HH + k]; }
            sA[k * SAS + node] = v0;
            sA[64 * SAS + k * SAS + node] = v1;
        }
        __syncthreads();

        ull acc[24];
        #pragma unroll
        for (int i = 0; i < 24; i++) acc[i] = 0ull;

        #pragma unroll 4
        for (int k = 0; k < 64; k++) {
            float4 av = *(const float4*)(sAh + k * SAS + ng * 4);
            ull ad0 = pk2(av.x, av.x);
            ull ad1 = pk2(av.y, av.y);
            ull ad2 = pk2(av.z, av.z);
            ull ad3 = pk2(av.w, av.w);
            float4 w0 = *(const float4*)(sW + k * WS + obase);
            float4 w1 = *(const float4*)(sW + k * WS + obase + 4);
            float4 w2 = *(const float4*)(sW + k * WS + obase + 8);
            const ull* wp0 = (const ull*)&w0;
            const ull* wp1 = (const ull*)&w1;
            const ull* wp2 = (const ull*)&w2;
            fma2(acc[0],  ad0, wp0[0]); fma2(acc[1],  ad0, wp0[1]);
            fma2(acc[2],  ad0, wp1[0]); fma2(acc[3],  ad0, wp1[1]);
            fma2(acc[4],  ad0, wp2[0]); fma2(acc[5],  ad0, wp2[1]);
            fma2(acc[6],  ad1, wp0[0]); fma2(acc[7],  ad1, wp0[1]);
            fma2(acc[8],  ad1, wp1[0]); fma2(acc[9],  ad1, wp1[1]);
            fma2(acc[10], ad1, wp2[0]); fma2(acc[11], ad1, wp2[1]);
            fma2(acc[12], ad2, wp0[0]); fma2(acc[13], ad2, wp0[1]);
            fma2(acc[14], ad2, wp1[0]); fma2(acc[15], ad2, wp1[1]);
            fma2(acc[16], ad2, wp2[0]); fma2(acc[17], ad2, wp2[1]);
            fma2(acc[18], ad3, wp0[0]); fma2(acc[19], ad3, wp0[1]);
            fma2(acc[20], ad3, wp1[0]); fma2(acc[21], ad3, wp1[1]);
            fma2(acc[22], ad3, wp2[0]); fma2(acc[23], ad3, wp2[1]);
        }

        // scatter accumulators to sG
        #pragma unroll
        for (int i = 0; i < 4; i++) {
            int node = ng * 4 + i;
            #pragma unroll
            for (int j = 0; j < 6; j++) {
                float2 v = un2(acc[i * 6 + j]);
                sG[node * 384 + obase + 2 * j]     = v.x;
                sG[node * 384 + obase + 2 * j + 1] = v.y;
            }
        }
        __syncthreads();

        // GRU elementwise
        for (int idx = tid; idx < MTILE * 64; idx += 256) {
            int node = idx >> 6, f = idx & 63;
            int gn = n0 + node;
            if (gn < n) {
                const float* gr = sG + node * 384;
                float ir = gr[f]        + bih[f];
                float iz = gr[64 + f]   + bih[64 + f];
                float in_ = gr[128 + f] + bih[128 + f];
                float hr = gr[192 + f]  + bhh[f];
                float hz = gr[256 + f]  + bhh[64 + f];
                float hn = gr[320 + f]  + bhh[128 + f];
                float hold = g_h[gn * HH + f];
                float r = sigm(ir + hr);
                float z = sigm(iz + hz);
                float nn = tanh_fast(in_ + fmaf(r, hn, 0.f));
                g_h[gn * HH + f] = fmaf(1.f - z, nn, z * hold);
            }
        }
        __syncthreads();
    }
}

// ---------------- final edge predictor ----------------
__global__ void k_pred(const int* __restrict__ src, const int* __restrict__ dst,
                       const float* __restrict__ bp, float* __restrict__ out, int e) {
    int i = blockIdx.x * blockDim.x + threadIdx.x;
    if (i < e) out[i] = g_a1[src[i]] + g_a2[dst[i]] + bp[0];
}

// ---------------- launch ----------------
extern "C" void kernel_launch(void* const* d_in, const int* in_sizes, int n_in,
                              void* d_out, int out_size) {
    const float* feat = (const float*)d_in[0];
    const int*   src  = (const int*)d_in[1];
    const int*   dst  = (const int*)d_in[2];
    const float* Win  = (const float*)d_in[3];
    const float* bin  = (const float*)d_in[4];
    const float* We   = (const float*)d_in[5];
    const float* be   = (const float*)d_in[6];
    const float* Wih  = (const float*)d_in[7];
    const float* Whh  = (const float*)d_in[8];
    const float* bih  = (const float*)d_in[9];
    const float* bhh  = (const float*)d_in[10];
    const float* Wp   = (const float*)d_in[11];
    const float* bp   = (const float*)d_in[12];
    float* out = (float*)d_out;

    int n = in_sizes[0] / INF;   // 50000
    int e = in_sizes[1];         // 800000

    int smem = (64 * WS + 2 * 64 * SAS + 32 * 384) * (int)sizeof(float);
    cudaFuncSetAttribute(k_gru, cudaFuncAttributeMaxDynamicSharedMemorySize, smem);

    // CSR build (indices are static, but rebuild each call: deterministic work)
    k_zero<<<(n + 255) / 256, 256>>>(n);
    k_count<<<(e + 255) / 256, 256>>>(dst, e);
    k_scan<<<1, 1024>>>(n);
    k_fill<<<(e + 255) / 256, 256>>>(src, dst, e);

    k_input<<<(n * HH + 255) / 256, 256>>>(feat, Win, bin, n);

    for (int l = 0; l < 3; l++) {
        k_dots<<<(n + 7) / 8, 256>>>(We, n);
        k_agg<<<(n + 7) / 8, 256>>>(be, n);
        k_gru<<<148, 256, smem>>>(Wih + l * 192 * 64, Whh + l * 192 * 64,
                                  bih + l * 192, bhh + l * 192, n);
    }

    k_dots<<<(n + 7) / 8, 256>>>(Wp, n);
    k_pred<<<(e + 255) / 256, 256>>>(src, dst, bp, out, e);
}

// round 3
// speedup vs baseline: 1.1027x; 1.1027x over previous
#include <cuda_runtime.h>
#include <cuda_bf16.h>
#include <cstdint>

#define NN 50000
#define EE 800000
#define INF 16
#define HH 64

// ---------------- scratch (static device globals; no allocs) ----------------
__device__ float g_h[NN * HH];
__device__ float g_hnew[NN * HH];
__device__ float g_a1[NN];
__device__ float g_a2[NN];
__device__ int   g_cnt[NN];
__device__ int   g_off[NN + 1];
__device__ int   g_cur[NN];
__device__ int   g_csr_src[EE];
__device__ float g_csr_w[EE];
__device__ int   g_perm[EE];

typedef unsigned long long ull;

__device__ __forceinline__ ull pk2(float a, float b) {
    ull r;
    asm("mov.b64 %0, {%1, %2};" : "=l"(r) : "f"(a), "f"(b));
    return r;
}
__device__ __forceinline__ void fma2(ull &d, ull a, ull b) {
    asm("fma.rn.f32x2 %0, %1, %2, %0;" : "+l"(d) : "l"(a), "l"(b));
}
__device__ __forceinline__ float2 un2(ull v) {
    float2 f;
    asm("mov.b64 {%0, %1}, %2;" : "=f"(f.x), "=f"(f.y) : "l"(v));
    return f;
}
__device__ __forceinline__ float sigm(float x) {
    return 1.0f / (1.0f + __expf(-x));
}
__device__ __forceinline__ float tanh_fast(float x) {
    return 2.0f / (1.0f + __expf(-2.0f * x)) - 1.0f;
}

// ---------------- CSR build ----------------
__global__ void k_zero(int n) {
    int i = blockIdx.x * blockDim.x + threadIdx.x;
    if (i < n) g_cnt[i] = 0;
}

__global__ void k_count(const int* __restrict__ dst, int e) {
    int i = blockIdx.x * blockDim.x + threadIdx.x;
    if (i < e) atomicAdd(&g_cnt[dst[i]], 1);
}

// single-block exclusive scan of g_cnt[0..n) -> g_off, g_cur ; g_off[n] = total
__global__ void k_scan(int n) {
    __shared__ int sh_carry;
    __shared__ int wsum[32];
    int tid = threadIdx.x;
    if (tid == 0) sh_carry = 0;
    __syncthreads();
    for (int base = 0; base < n; base += 1024) {
        int i = base + tid;
        int v = (i < n) ? g_cnt[i] : 0;
        int x = v;
        #pragma unroll
        for (int d = 1; d < 32; d <<= 1) {
            int y = __shfl_up_sync(0xffffffffu, x, d);
            if ((tid & 31) >= d) x += y;
        }
        if ((tid & 31) == 31) wsum[tid >> 5] = x;
        __syncthreads();
        if (tid < 32) {
            int y = wsum[tid];
            #pragma unroll
            for (int d = 1; d < 32; d <<= 1) {
                int z = __shfl_up_sync(0xffffffffu, y, d);
                if (tid >= d) y += z;
            }
            wsum[tid] = y;
        }
        __syncthreads();
        int excl = ((tid >> 5) ? wsum[(tid >> 5) - 1] : 0) + (x - v);
        int carry = sh_carry;
        if (i < n) { g_off[i] = carry + excl; g_cur[i] = carry + excl; }
        __syncthreads();
        if (tid == 1023) sh_carry = carry + excl + v;
        __syncthreads();
    }
    if (tid == 0) g_off[n] = sh_carry;
}

__global__ void k_fill(const int* __restrict__ src, const int* __restrict__ dst, int e) {
    int i = blockIdx.x * blockDim.x + threadIdx.x;
    if (i < e) {
        int d = dst[i];
        int p = atomicAdd(&g_cur[d], 1);
        g_csr_src[p] = src[i];
        g_perm[i] = p;
    }
}

// ---------------- input linear: h = feat @ W_in + b_in ----------------
__global__ void k_input(const float* __restrict__ feat, const float* __restrict__ Win,
                        const float* __restrict__ bin, int n) {
    __shared__ float sw[INF * HH];
    __shared__ float sb[HH];
    int tid = threadIdx.x;
    for (int i = tid; i < INF * HH; i += 256) sw[i] = Win[i];
    if (tid < HH) sb[tid] = bin[tid];
    __syncthreads();
    int idx = blockIdx.x * 256 + tid;
    if (idx < n * HH) {
        int node = idx >> 6, f = idx & 63;
        float acc = sb[f];
        const float* fr = feat + node * INF;
        #pragma unroll
        for (int i = 0; i < INF; i++) acc = fmaf(fr[i], sw[i * HH + f], acc);
        g_h[idx] = acc;
    }
}

// ---------------- per-node dots: a1 = h . W[0:64], a2 = h . W[64:128] ----------------
__global__ void k_dots(const float* __restrict__ W, int n) {
    __shared__ float sw[128];
    int tid = threadIdx.x;
    if (tid < 128) sw[tid] = W[tid];
    __syncthreads();
    int v = blockIdx.x * 8 + (tid >> 5);
    int lane = tid & 31;
    if (v >= n) return;
    float h0 = g_h[v * HH + lane];
    float h1 = g_h[v * HH + 32 + lane];
    float s1 = h0 * sw[lane] + h1 * sw[32 + lane];
    float s2 = h0 * sw[64 + lane] + h1 * sw[96 + lane];
    #pragma unroll
    for (int d = 16; d; d >>= 1) {
        s1 += __shfl_xor_sync(0xffffffffu, s1, d);
        s2 += __shfl_xor_sync(0xffffffffu, s2, d);
    }
    if (lane == 0) { g_a1[v] = s1; g_a2[v] = s2; }
}

// ---------------- edge weights in CSR order (edge-parallel, coalesced) -------
__global__ void k_w(const int* __restrict__ src, const int* __restrict__ dst,
                    const float* __restrict__ be, int e) {
    int i = blockIdx.x * blockDim.x + threadIdx.x;
    if (i < e) {
        float v = g_a1[src[i]] + g_a2[dst[i]] + be[0];
        g_csr_w[g_perm[i]] = sigm(v);
    }
}

// ---------------- aggregation: hnew[v] = sum_e w_e * h[src_e] ----------------
// warp per node, 2 edges per iteration (half-warp float4 each)
__global__ void k_agg(int n) {
    int v = blockIdx.x * 8 + (threadIdx.x >> 5);
    int lane = threadIdx.x & 31;
    if (v >= n) return;
    int j0 = g_off[v], j1 = g_off[v + 1];
    int half = lane >> 4, hl = lane & 15;
    float4 acc = make_float4(0.f, 0.f, 0.f, 0.f);
    for (int j = j0; j < j1; j += 2) {
        int jj = j + half;
        int s = 0;
        float w = 0.f;
        if (jj < j1) {
            s = __ldg(&g_csr_src[jj]);
            w = __ldg(&g_csr_w[jj]);
        }
        float4 hv = *(const float4*)&g_h[s * HH + hl * 4];
        acc.x = fmaf(w, hv.x, acc.x);
        acc.y = fmaf(w, hv.y, acc.y);
        acc.z = fmaf(w, hv.z, acc.z);
        acc.w = fmaf(w, hv.w, acc.w);
    }
    acc.x += __shfl_xor_sync(0xffffffffu, acc.x, 16);
    acc.y += __shfl_xor_sync(0xffffffffu, acc.y, 16);
    acc.z += __shfl_xor_sync(0xffffffffu, acc.z, 16);
    acc.w += __shfl_xor_sync(0xffffffffu, acc.w, 16);
    if (half == 0) *(float4*)&g_hnew[v * HH + hl * 4] = acc;
}

// ---------------- fused GRU + next-layer dots ----------------
// MTILE=64 nodes per tile. Thread owns 4 nodes x 4 features x all 6 gate groups
// so GRU gates are computed entirely in registers (no G tile in smem).
#define MT 64
#define WS 388   // 384 outputs + pad
#define SAS 68   // 64 nodes + pad

__global__ void __launch_bounds__(256, 1)
k_gru(const float* __restrict__ Wih, const float* __restrict__ Whh,
      const float* __restrict__ bih, const float* __restrict__ bhh,
      const float* __restrict__ Wd, int n) {
    extern __shared__ float sm[];
    float* sW  = sm;                      // [64 k][WS]: cols g*64+f ; g<3 Wih, g>=3 Whh
    float* sA  = sm + 64 * WS;            // [2][64 k][SAS] (hnew, h) k-major
    float* sWe = sA + 2 * 64 * SAS;       // [128] dot weights for next layer
    float* sd1 = sWe + 128;               // [64]
    float* sd2 = sd1 + 64;                // [64]

    int tid = threadIdx.x;
    int og = tid >> 4;         // 0..15 -> features f0..f0+3
    int ng = tid & 15;         // 0..15 -> nodes ng*4..ng*4+3
    int f0 = og * 4;

    for (int idx = tid; idx < 192 * 64; idx += 256) {
        int o = idx >> 6, k = idx & 63;
        sW[k * WS + o]       = Wih[idx];
        sW[k * WS + 192 + o] = Whh[idx];
    }
    if (tid < 128) sWe[tid] = Wd[tid];

    // per-thread bias registers (float4 per gate group)
    float4 bI0 = *(const float4*)&bih[f0];
    float4 bI1 = *(const float4*)&bih[64 + f0];
    float4 bI2 = *(const float4*)&bih[128 + f0];
    float4 bH0 = *(const float4*)&bhh[f0];
    float4 bH1 = *(const float4*)&bhh[64 + f0];
    float4 bH2 = *(const float4*)&bhh[128 + f0];
    __syncthreads();

    int ntiles = (n + MT - 1) / MT;
    for (int tile = blockIdx.x; tile < ntiles; tile += gridDim.x) {
        int n0 = tile * MT;
        // zero the per-tile dot accumulators BEFORE the sync that opens the tile
        if (tid < 64) { sd1[tid] = 0.f; sd2[tid] = 0.f; }

        for (int idx = tid; idx < MT * 64; idx += 256) {
            int node = idx >> 6, k = idx & 63;
            int gn = n0 + node;
            float v0 = 0.f, v1 = 0.f;
            if (gn < n) { v0 = g_hnew[gn * HH + k]; v1 = g_h[gn * HH + k]; }
            sA[k * SAS + node] = v0;
            sA[64 * SAS + k * SAS + node] = v1;
        }
        __syncthreads();

        ull acc[48];   // [g][node i][pair j] = acc[g*8 + i*2 + j]
        #pragma unroll
        for (int i = 0; i < 48; i++) acc[i] = 0ull;

        #pragma unroll 2
        for (int k = 0; k < 64; k++) {
            float4 an = *(const float4*)&sA[k * SAS + ng * 4];
            float4 ah = *(const float4*)&sA[64 * SAS + k * SAS + ng * 4];
            ull pn[4] = { pk2(an.x, an.x), pk2(an.y, an.y), pk2(an.z, an.z), pk2(an.w, an.w) };
            ull ph[4] = { pk2(ah.x, ah.x), pk2(ah.y, ah.y), pk2(ah.z, ah.z), pk2(ah.w, ah.w) };
            const float* wb = sW + k * WS + f0;
            #pragma unroll
            for (int g = 0; g < 3; g++) {
                float4 w = *(const float4*)(wb + g * 64);
                const ull* wp = (const ull*)&w;
                #pragma unroll
                for (int i = 0; i < 4; i++) {
                    fma2(acc[g * 8 + i * 2 + 0], pn[i], wp[0]);
                    fma2(acc[g * 8 + i * 2 + 1], pn[i], wp[1]);
                }
            }
            #pragma unroll
            for (int g = 3; g < 6; g++) {
                float4 w = *(const float4*)(wb + 192 + (g - 3) * 64);
                const ull* wp = (const ull*)&w;
                #pragma unroll
                for (int i = 0; i < 4; i++) {
                    fma2(acc[g * 8 + i * 2 + 0], ph[i], wp[0]);
                    fma2(acc[g * 8 + i * 2 + 1], ph[i], wp[1]);
                }
            }
        }

        const float* bIp[3] = { (const float*)&bI0, (const float*)&bI1, (const float*)&bI2 };
        const float* bHp[3] = { (const float*)&bH0, (const float*)&bH1, (const float*)&bH2 };

        #pragma unroll
        for (int i = 0; i < 4; i++) {
            int node = ng * 4 + i;
            int gn = n0 + node;
            float ga[6][4];
            #pragma unroll
            for (int g = 0; g < 6; g++) {
                float2 t0 = un2(acc[g * 8 + i * 2 + 0]);
                float2 t1 = un2(acc[g * 8 + i * 2 + 1]);
                ga[g][0] = t0.x; ga[g][1] = t0.y; ga[g][2] = t1.x; ga[g][3] = t1.y;
            }
            float ho[4];
            #pragma unroll
            for (int q = 0; q < 4; q++) {
                float ir = ga[0][q] + bIp[0][q];
                float iz = ga[1][q] + bIp[1][q];
                float in_ = ga[2][q] + bIp[2][q];
                float hr = ga[3][q] + bHp[0][q];
                float hz = ga[4][q] + bHp[1][q];
                float hn = ga[5][q] + bHp[2][q];
                float hold = sA[64 * SAS + (f0 + q) * SAS + node];
                float r = sigm(ir + hr);
                float z = sigm(iz + hz);
                float nn_ = tanh_fast(fmaf(r, hn, in_));
                ho[q] = fmaf(1.f - z, nn_, z * hold);
            }
            if (gn < n) {
                float4 o4 = make_float4(ho[0], ho[1], ho[2], ho[3]);
                *(float4*)&g_h[gn * HH + f0] = o4;
                float p1 = ho[0] * sWe[f0] + ho[1] * sWe[f0 + 1]
                         + ho[2] * sWe[f0 + 2] + ho[3] * sWe[f0 + 3];
                float p2 = ho[0] * sWe[64 + f0] + ho[1] * sWe[64 + f0 + 1]
                         + ho[2] * sWe[64 + f0 + 2] + ho[3] * sWe[64 + f0 + 3];
                atomicAdd(&sd1[node], p1);
                atomicAdd(&sd2[node], p2);
            }
        }
        __syncthreads();

        if (tid < 64 && n0 + tid < n) {
            g_a1[n0 + tid] = sd1[tid];
            g_a2[n0 + tid] = sd2[tid];
        }
        __syncthreads();
    }
}

// ---------------- final edge predictor ----------------
__global__ void k_pred(const int* __restrict__ src, const int* __restrict__ dst,
                       const float* __restrict__ bp, float* __restrict__ out, int e) {
    int i = blockIdx.x * blockDim.x + threadIdx.x;
    if (i < e) out[i] = g_a1[src[i]] + g_a2[dst[i]] + bp[0];
}

// ---------------- launch ----------------
extern "C" void kernel_launch(void* const* d_in, const int* in_sizes, int n_in,
                              void* d_out, int out_size) {
    const float* feat = (const float*)d_in[0];
    const int*   src  = (const int*)d_in[1];
    const int*   dst  = (const int*)d_in[2];
    const float* Win  = (const float*)d_in[3];
    const float* bin  = (const float*)d_in[4];
    const float* We   = (const float*)d_in[5];
    const float* be   = (const float*)d_in[6];
    const float* Wih  = (const float*)d_in[7];
    const float* Whh  = (const float*)d_in[8];
    const float* bih  = (const float*)d_in[9];
    const float* bhh  = (const float*)d_in[10];
    const float* Wp   = (const float*)d_in[11];
    const float* bp   = (const float*)d_in[12];
    float* out = (float*)d_out;

    int n = in_sizes[0] / INF;   // 50000
    int e = in_sizes[1];         // 800000

    int smem = (64 * WS + 2 * 64 * SAS + 128 + 128) * (int)sizeof(float);
    cudaFuncSetAttribute(k_gru, cudaFuncAttributeMaxDynamicSharedMemorySize, smem);

    // CSR build
    k_zero<<<(n + 255) / 256, 256>>>(n);
    k_count<<<(e + 255) / 256, 256>>>(dst, e);
    k_scan<<<1, 1024>>>(n);
    k_fill<<<(e + 255) / 256, 256>>>(src, dst, e);

    k_input<<<(n * HH + 255) / 256, 256>>>(feat, Win, bin, n);
    k_dots<<<(n + 7) / 8, 256>>>(We, n);   // a1/a2 for layer 0

    for (int l = 0; l < 3; l++) {
        k_w<<<(e + 255) / 256, 256>>>(src, dst, be, e);
        k_agg<<<(n + 7) / 8, 256>>>(n);
        // fused GRU + dots for next layer (last layer uses predictor weights)
        const float* Wd = (l == 2) ? Wp : We;
        k_gru<<<148, 256, smem>>>(Wih + l * 192 * 64, Whh + l * 192 * 64,
                                  bih + l * 192, bhh + l * 192, Wd, n);
    }

    k_pred<<<(e + 255) / 256, 256>>>(src, dst, bp, out, e);
}

// round 4
// speedup vs baseline: 1.1248x; 1.0200x over previous
#include <cuda_runtime.h>
#include <cuda_bf16.h>
#include <cstdint>

#define NN 50000
#define EE 800000
#define INF 16
#define HH 64

// ---------------- scratch (static device globals; no allocs) ----------------
__device__ float g_h[NN * HH];
__device__ float g_hnew[NN * HH];
__device__ float g_a1[NN];
__device__ float g_a2[NN];
__device__ int   g_cnt[NN];
__device__ int   g_off[NN + 1];
__device__ int   g_cur[NN];
__device__ int   g_csr_src[EE];
__device__ int   g_bsum[64];

typedef unsigned long long ull;

__device__ __forceinline__ ull pk2(float a, float b) {
    ull r;
    asm("mov.b64 %0, {%1, %2};" : "=l"(r) : "f"(a), "f"(b));
    return r;
}
__device__ __forceinline__ void fma2(ull &d, ull a, ull b) {
    asm("fma.rn.f32x2 %0, %1, %2, %0;" : "+l"(d) : "l"(a), "l"(b));
}
__device__ __forceinline__ float2 un2(ull v) {
    float2 f;
    asm("mov.b64 {%0, %1}, %2;" : "=f"(f.x), "=f"(f.y) : "l"(v));
    return f;
}
__device__ __forceinline__ float sigm(float x) {
    return 1.0f / (1.0f + __expf(-x));
}
__device__ __forceinline__ float tanh_fast(float x) {
    return 2.0f / (1.0f + __expf(-2.0f * x)) - 1.0f;
}

// ---------------- CSR build ----------------
__global__ void k_zero(int n) {
    int i = blockIdx.x * blockDim.x + threadIdx.x;
    if (i < n) g_cnt[i] = 0;
}

__global__ void k_count(const int* __restrict__ dst, int e) {
    int i = blockIdx.x * blockDim.x + threadIdx.x;
    if (i < e) atomicAdd(&g_cnt[dst[i]], 1);
}

// phase 1: per-block exclusive scan of g_cnt -> g_off (block-local), block sums -> g_bsum
__global__ void k_scan1(int n) {
    __shared__ int wsum[32];
    int t = threadIdx.x;
    int i = blockIdx.x * 1024 + t;
    int v = (i < n) ? g_cnt[i] : 0;
    int x = v;
    #pragma unroll
    for (int d = 1; d < 32; d <<= 1) {
        int y = __shfl_up_sync(0xffffffffu, x, d);
        if ((t & 31) >= d) x += y;
    }
    if ((t & 31) == 31) wsum[t >> 5] = x;
    __syncthreads();
    if (t < 32) {
        int y = wsum[t];
        #pragma unroll
        for (int d = 1; d < 32; d <<= 1) {
            int z = __shfl_up_sync(0xffffffffu, y, d);
            if (t >= d) y += z;
        }
        wsum[t] = y;
    }
    __syncthreads();
    int excl = ((t >> 5) ? wsum[(t >> 5) - 1] : 0) + (x - v);
    if (i < n) g_off[i] = excl;
    if (t == 1023) g_bsum[blockIdx.x] = excl + v;   // block total (v=0 past n)
}

// phase 2: serial exclusive scan of 49 block sums (trivial)
__global__ void k_scan2(int nb, int n) {
    if (threadIdx.x == 0) {
        int run = 0;
        for (int b = 0; b < nb; b++) { int c = g_bsum[b]; g_bsum[b] = run; run += c; }
        g_off[n] = run;
    }
}

// phase 3: add block offsets
__global__ void k_scan3(int n) {
    int i = blockIdx.x * 1024 + threadIdx.x;
    if (i < n) {
        int o = g_off[i] + g_bsum[blockIdx.x];
        g_off[i] = o;
        g_cur[i] = o;
    }
}

__global__ void k_fill(const int* __restrict__ src, const int* __restrict__ dst, int e) {
    int i = blockIdx.x * blockDim.x + threadIdx.x;
    if (i < e) {
        int d = dst[i];
        int p = atomicAdd(&g_cur[d], 1);
        g_csr_src[p] = src[i];
    }
}

// ---------------- input linear: h = feat @ W_in + b_in ----------------
__global__ void k_input(const float* __restrict__ feat, const float* __restrict__ Win,
                        const float* __restrict__ bin, int n) {
    __shared__ float sw[INF * HH];
    __shared__ float sb[HH];
    int tid = threadIdx.x;
    for (int i = tid; i < INF * HH; i += 256) sw[i] = Win[i];
    if (tid < HH) sb[tid] = bin[tid];
    __syncthreads();
    int idx = blockIdx.x * 256 + tid;
    if (idx < n * HH) {
        int node = idx >> 6, f = idx & 63;
        float acc = sb[f];
        const float* fr = feat + node * INF;
        #pragma unroll
        for (int i = 0; i < INF; i++) acc = fmaf(fr[i], sw[i * HH + f], acc);
        g_h[idx] = acc;
    }
}

// ---------------- per-node dots (layer 0 only) ----------------
__global__ void k_dots(const float* __restrict__ W, int n) {
    __shared__ float sw[128];
    int tid = threadIdx.x;
    if (tid < 128) sw[tid] = W[tid];
    __syncthreads();
    int v = blockIdx.x * 8 + (tid >> 5);
    int lane = tid & 31;
    if (v >= n) return;
    float h0 = g_h[v * HH + lane];
    float h1 = g_h[v * HH + 32 + lane];
    float s1 = h0 * sw[lane] + h1 * sw[32 + lane];
    float s2 = h0 * sw[64 + lane] + h1 * sw[96 + lane];
    #pragma unroll
    for (int d = 16; d; d >>= 1) {
        s1 += __shfl_xor_sync(0xffffffffu, s1, d);
        s2 += __shfl_xor_sync(0xffffffffu, s2, d);
    }
    if (lane == 0) { g_a1[v] = s1; g_a2[v] = s2; }
}

// ---------------- aggregation with inline edge weights -----------------------
// warp per node; 2 halves x unroll-2 = 4 independent edge chains in flight.
__global__ void k_agg(const float* __restrict__ be, int n) {
    int v = blockIdx.x * 8 + (threadIdx.x >> 5);
    int lane = threadIdx.x & 31;
    if (v >= n) return;
    float a2v = g_a2[v] + be[0];
    int j0 = g_off[v], j1 = g_off[v + 1];
    int half = lane >> 4, hl = lane & 15;
    float4 acc0 = make_float4(0.f, 0.f, 0.f, 0.f);
    float4 acc1 = make_float4(0.f, 0.f, 0.f, 0.f);
    int j = j0 + half;                 // this half's edges: j, j+2, j+4, ...
    for (; j + 2 < j1; j += 4) {       // two edges per iter, independent chains
        int s0 = __ldg(&g_csr_src[j]);
        int s1 = __ldg(&g_csr_src[j + 2]);
        float w0 = sigm(__ldg(&g_a1[s0]) + a2v);
        float w1 = sigm(__ldg(&g_a1[s1]) + a2v);
        float4 h0 = *(const float4*)&g_h[s0 * HH + hl * 4];
        float4 h1 = *(const float4*)&g_h[s1 * HH + hl * 4];
        acc0.x = fmaf(w0, h0.x, acc0.x); acc0.y = fmaf(w0, h0.y, acc0.y);
        acc0.z = fmaf(w0, h0.z, acc0.z); acc0.w = fmaf(w0, h0.w, acc0.w);
        acc1.x = fmaf(w1, h1.x, acc1.x); acc1.y = fmaf(w1, h1.y, acc1.y);
        acc1.z = fmaf(w1, h1.z, acc1.z); acc1.w = fmaf(w1, h1.w, acc1.w);
    }
    if (j < j1) {
        int s = __ldg(&g_csr_src[j]);
        float w = sigm(__ldg(&g_a1[s]) + a2v);
        float4 hv = *(const float4*)&g_h[s * HH + hl * 4];
        acc0.x = fmaf(w, hv.x, acc0.x); acc0.y = fmaf(w, hv.y, acc0.y);
        acc0.z = fmaf(w, hv.z, acc0.z); acc0.w = fmaf(w, hv.w, acc0.w);
    }
    acc0.x += acc1.x; acc0.y += acc1.y; acc0.z += acc1.z; acc0.w += acc1.w;
    acc0.x += __shfl_xor_sync(0xffffffffu, acc0.x, 16);
    acc0.y += __shfl_xor_sync(0xffffffffu, acc0.y, 16);
    acc0.z += __shfl_xor_sync(0xffffffffu, acc0.z, 16);
    acc0.w += __shfl_xor_sync(0xffffffffu, acc0.w, 16);
    if (half == 0) *(float4*)&g_hnew[v * HH + hl * 4] = acc0;
}

// ---------------- fused GRU + next-layer dots ----------------
#define MT 64
#define WS 388   // 384 outputs + pad
#define SAS 68   // 64 nodes + pad

__global__ void __launch_bounds__(256, 1)
k_gru(const float* __restrict__ Wih, const float* __restrict__ Whh,
      const float* __restrict__ bih, const float* __restrict__ bhh,
      const float* __restrict__ Wd, int n) {
    extern __shared__ float sm[];
    float* sW  = sm;                      // [64 k][WS]: cols g*64+f ; g<3 Wih, g>=3 Whh
    float* sA  = sm + 64 * WS;            // [2][64 k][SAS] (hnew, h) k-major
    float* sWe = sA + 2 * 64 * SAS;       // [128] dot weights for next layer
    float* sd1 = sWe + 128;               // [64]
    float* sd2 = sd1 + 64;                // [64]

    int tid = threadIdx.x;
    int og = tid >> 4;         // 0..15 -> features f0..f0+3
    int ng = tid & 15;         // 0..15 -> nodes ng*4..ng*4+3
    int f0 = og * 4;

    for (int idx = tid; idx < 192 * 64; idx += 256) {
        int o = idx >> 6, k = idx & 63;
        sW[k * WS + o]       = Wih[idx];
        sW[k * WS + 192 + o] = Whh[idx];
    }
    if (tid < 128) sWe[tid] = Wd[tid];

    float4 bI0 = *(const float4*)&bih[f0];
    float4 bI1 = *(const float4*)&bih[64 + f0];
    float4 bI2 = *(const float4*)&bih[128 + f0];
    float4 bH0 = *(const float4*)&bhh[f0];
    float4 bH1 = *(const float4*)&bhh[64 + f0];
    float4 bH2 = *(const float4*)&bhh[128 + f0];
    __syncthreads();

    int ntiles = (n + MT - 1) / MT;
    for (int tile = blockIdx.x; tile < ntiles; tile += gridDim.x) {
        int n0 = tile * MT;
        if (tid < 64) { sd1[tid] = 0.f; sd2[tid] = 0.f; }

        for (int idx = tid; idx < MT * 64; idx += 256) {
            int node = idx >> 6, k = idx & 63;
            int gn = n0 + node;
            float v0 = 0.f, v1 = 0.f;
            if (gn < n) { v0 = g_hnew[gn * HH + k]; v1 = g_h[gn * HH + k]; }
            sA[k * SAS + node] = v0;
            sA[64 * SAS + k * SAS + node] = v1;
        }
        __syncthreads();

        ull acc[48];
        #pragma unroll
        for (int i = 0; i < 48; i++) acc[i] = 0ull;

        #pragma unroll 2
        for (int k = 0; k < 64; k++) {
            float4 an = *(const float4*)&sA[k * SAS + ng * 4];
            float4 ah = *(const float4*)&sA[64 * SAS + k * SAS + ng * 4];
            ull pn[4] = { pk2(an.x, an.x), pk2(an.y, an.y), pk2(an.z, an.z), pk2(an.w, an.w) };
            ull ph[4] = { pk2(ah.x, ah.x), pk2(ah.y, ah.y), pk2(ah.z, ah.z), pk2(ah.w, ah.w) };
            const float* wb = sW + k * WS + f0;
            #pragma unroll
            for (int g = 0; g < 3; g++) {
                float4 w = *(const float4*)(wb + g * 64);
                const ull* wp = (const ull*)&w;
                #pragma unroll
                for (int i = 0; i < 4; i++) {
                    fma2(acc[g * 8 + i * 2 + 0], pn[i], wp[0]);
                    fma2(acc[g * 8 + i * 2 + 1], pn[i], wp[1]);
                }
            }
            #pragma unroll
            for (int g = 3; g < 6; g++) {
                float4 w = *(const float4*)(wb + 192 + (g - 3) * 64);
                const ull* wp = (const ull*)&w;
                #pragma unroll
                for (int i = 0; i < 4; i++) {
                    fma2(acc[g * 8 + i * 2 + 0], ph[i], wp[0]);
                    fma2(acc[g * 8 + i * 2 + 1], ph[i], wp[1]);
                }
            }
        }

        const float* bIp[3] = { (const float*)&bI0, (const float*)&bI1, (const float*)&bI2 };
        const float* bHp[3] = { (const float*)&bH0, (const float*)&bH1, (const float*)&bH2 };

        #pragma unroll
        for (int i = 0; i < 4; i++) {
            int node = ng * 4 + i;
            int gn = n0 + node;
            float ga[6][4];
            #pragma unroll
            for (int g = 0; g < 6; g++) {
                float2 t0 = un2(acc[g * 8 + i * 2 + 0]);
                float2 t1 = un2(acc[g * 8 + i * 2 + 1]);
                ga[g][0] = t0.x; ga[g][1] = t0.y; ga[g][2] = t1.x; ga[g][3] = t1.y;
            }
            float ho[4];
            #pragma unroll
            for (int q = 0; q < 4; q++) {
                float ir = ga[0][q] + bIp[0][q];
                float iz = ga[1][q] + bIp[1][q];
                float in_ = ga[2][q] + bIp[2][q];
                float hr = ga[3][q] + bHp[0][q];
                float hz = ga[4][q] + bHp[1][q];
                float hn = ga[5][q] + bHp[2][q];
                float hold = sA[64 * SAS + (f0 + q) * SAS + node];
                float r = sigm(ir + hr);
                float z = sigm(iz + hz);
                float nn_ = tanh_fast(fmaf(r, hn, in_));
                ho[q] = fmaf(1.f - z, nn_, z * hold);
            }
            if (gn < n) {
                float4 o4 = make_float4(ho[0], ho[1], ho[2], ho[3]);
                *(float4*)&g_h[gn * HH + f0] = o4;
                float p1 = ho[0] * sWe[f0] + ho[1] * sWe[f0 + 1]
                         + ho[2] * sWe[f0 + 2] + ho[3] * sWe[f0 + 3];
                float p2 = ho[0] * sWe[64 + f0] + ho[1] * sWe[64 + f0 + 1]
                         + ho[2] * sWe[64 + f0 + 2] + ho[3] * sWe[64 + f0 + 3];
                atomicAdd(&sd1[node], p1);
                atomicAdd(&sd2[node], p2);
            }
        }
        __syncthreads();

        if (tid < 64 && n0 + tid < n) {
            g_a1[n0 + tid] = sd1[tid];
            g_a2[n0 + tid] = sd2[tid];
        }
        __syncthreads();
    }
}

// ---------------- final edge predictor ----------------
__global__ void k_pred(const int* __restrict__ src, const int* __restrict__ dst,
                       const float* __restrict__ bp, float* __restrict__ out, int e) {
    int i = blockIdx.x * blockDim.x + threadIdx.x;
    if (i < e) out[i] = g_a1[src[i]] + g_a2[dst[i]] + bp[0];
}

// ---------------- launch ----------------
extern "C" void kernel_launch(void* const* d_in, const int* in_sizes, int n_in,
                              void* d_out, int out_size) {
    const float* feat = (const float*)d_in[0];
    const int*   src  = (const int*)d_in[1];
    const int*   dst  = (const int*)d_in[2];
    const float* Win  = (const float*)d_in[3];
    const float* bin  = (const float*)d_in[4];
    const float* We   = (const float*)d_in[5];
    const float* be   = (const float*)d_in[6];
    const float* Wih  = (const float*)d_in[7];
    const float* Whh  = (const float*)d_in[8];
    const float* bih  = (const float*)d_in[9];
    const float* bhh  = (const float*)d_in[10];
    const float* Wp   = (const float*)d_in[11];
    const float* bp   = (const float*)d_in[12];
    float* out = (float*)d_out;

    int n = in_sizes[0] / INF;   // 50000
    int e = in_sizes[1];         // 800000
    int nb = (n + 1023) / 1024;  // scan blocks

    int smem = (64 * WS + 2 * 64 * SAS + 128 + 128) * (int)sizeof(float);
    cudaFuncSetAttribute(k_gru, cudaFuncAttributeMaxDynamicSharedMemorySize, smem);

    // CSR build (multi-block scan)
    k_zero<<<(n + 255) / 256, 256>>>(n);
    k_count<<<(e + 255) / 256, 256>>>(dst, e);
    k_scan1<<<nb, 1024>>>(n);
    k_scan2<<<1, 32>>>(nb, n);
    k_scan3<<<nb, 1024>>>(n);
    k_fill<<<(e + 255) / 256, 256>>>(src, dst, e);

    k_input<<<(n * HH + 255) / 256, 256>>>(feat, Win, bin, n);
    k_dots<<<(n + 7) / 8, 256>>>(We, n);   // a1/a2 for layer 0

    for (int l = 0; l < 3; l++) {
        k_agg<<<(n + 7) / 8, 256>>>(be, n);
        const float* Wd = (l == 2) ? Wp : We;
        k_gru<<<148, 256, smem>>>(Wih + l * 192 * 64, Whh + l * 192 * 64,
                                  bih + l * 192, bhh + l * 192, Wd, n);
    }

    k_pred<<<(e + 255) / 256, 256>>>(src, dst, bp, out, e);
}